// round 2
// baseline (speedup 1.0000x reference)
#include <cuda_runtime.h>
#include <cuda_bf16.h>
#include <math.h>

#define B_   2
#define S_   2048
#define EMB_ 1024
#define HID_ 4096
#define NH_  16
#define DK_  64
#define ROWS_ (B_*S_)   // 4096

// ---------------- scratch (static device arrays; no allocation APIs) ---------
__device__ float g_xn[ROWS_*EMB_];
__device__ float g_q [ROWS_*EMB_];
__device__ float g_k [ROWS_*EMB_];
__device__ float g_v [ROWS_*EMB_];
__device__ float g_ao[ROWS_*EMB_];
__device__ float g_h [ROWS_*EMB_];
__device__ float g_hn[ROWS_*EMB_];
__device__ float g_ff[ROWS_*HID_];

// ---------------- block-wide sum --------------------------------------------
__device__ __forceinline__ float block_sum(float val) {
    __shared__ float red[8];
    int lane = threadIdx.x & 31, w = threadIdx.x >> 5;
    #pragma unroll
    for (int o = 16; o; o >>= 1) val += __shfl_xor_sync(0xffffffffu, val, o);
    if (lane == 0) red[w] = val;
    __syncthreads();
    if (w == 0) {
        float t = (lane < 8) ? red[lane] : 0.f;
        #pragma unroll
        for (int o = 4; o; o >>= 1) t += __shfl_xor_sync(0xffffffffu, t, o);
        if (lane == 0) red[0] = t;
    }
    __syncthreads();
    float r = red[0];
    __syncthreads();
    return r;
}

// ---------------- LayerNorm: one block (256 thr) per row of 1024 -------------
// Matches reference: var = sum((x-mean)^2)/(N-1); y = a*(x-mean)/(sqrt(var)+eps)+b
__global__ __launch_bounds__(256) void ln_kernel(
    const float* __restrict__ x, float* __restrict__ y,
    const float* __restrict__ a, const float* __restrict__ b)
{
    int row = blockIdx.x;
    const float4* xr = (const float4*)(x + (size_t)row * EMB_);
    float4 v = xr[threadIdx.x];
    float s = v.x + v.y + v.z + v.w;
    float total = block_sum(s);
    float mean = total * (1.0f / EMB_);
    float4 d;
    d.x = v.x - mean; d.y = v.y - mean; d.z = v.z - mean; d.w = v.w - mean;
    float ss = d.x*d.x + d.y*d.y + d.z*d.z + d.w*d.w;
    float sstot = block_sum(ss);
    float var = sstot * (1.0f / (EMB_ - 1));
    float scale = a[0] / (sqrtf(var) + 1e-6f);
    float bb = b[0];
    float4 o;
    o.x = d.x * scale + bb; o.y = d.y * scale + bb;
    o.z = d.z * scale + bb; o.w = d.w * scale + bb;
    ((float4*)(y + (size_t)row * EMB_))[threadIdx.x] = o;
}

// ---------------- SGEMM 128x128x8, 8x8 per thread, fused epilogue ------------
// C[M,N] = A[M,K] @ B[K,N]  (+bias[col]) (relu) (+res)
// M,N divisible by 128; K divisible by 8.
__global__ __launch_bounds__(256) void sgemm_kernel(
    int M, int N, int K,
    const float* __restrict__ A, const float* __restrict__ B,
    float* __restrict__ C,
    const float* __restrict__ bias, const float* __restrict__ res, int relu)
{
    __shared__ float As[8][128];
    __shared__ float Bs[8][128];

    int bm = blockIdx.y, bn = blockIdx.x;
    int tid = threadIdx.x;
    int tx = tid & 15, ty = tid >> 4;

    const float* Aptr = A + (size_t)bm * 128 * K;
    const float* Bptr = B + (size_t)bn * 128;

    int aRow = tid >> 1;          // 0..127
    int aCol = (tid & 1) * 4;     // 0 / 4
    int bRow = tid >> 5;          // 0..7
    int bCol = (tid & 31) * 4;    // 0..124

    float acc[8][8];
    #pragma unroll
    for (int i = 0; i < 8; i++)
        #pragma unroll
        for (int j = 0; j < 8; j++) acc[i][j] = 0.f;

    for (int kt = 0; kt < K; kt += 8) {
        float4 av = *(const float4*)(Aptr + (size_t)aRow * K + kt + aCol);
        As[aCol + 0][aRow] = av.x;
        As[aCol + 1][aRow] = av.y;
        As[aCol + 2][aRow] = av.z;
        As[aCol + 3][aRow] = av.w;
        float4 bv = *(const float4*)(Bptr + (size_t)(kt + bRow) * N + bCol);
        *(float4*)&Bs[bRow][bCol] = bv;
        __syncthreads();

        #pragma unroll
        for (int k = 0; k < 8; k++) {
            float ra[8], rb[8];
            *(float4*)(ra + 0) = *(const float4*)&As[k][ty * 4];
            *(float4*)(ra + 4) = *(const float4*)&As[k][64 + ty * 4];
            *(float4*)(rb + 0) = *(const float4*)&Bs[k][tx * 4];
            *(float4*)(rb + 4) = *(const float4*)&Bs[k][64 + tx * 4];
            #pragma unroll
            for (int i = 0; i < 8; i++)
                #pragma unroll
                for (int j = 0; j < 8; j++)
                    acc[i][j] = fmaf(ra[i], rb[j], acc[i][j]);
        }
        __syncthreads();
    }

    // epilogue
    #pragma unroll
    for (int i = 0; i < 8; i++) {
        int row = bm * 128 + ((i < 4) ? (ty * 4 + i) : (64 + ty * 4 + i - 4));
        #pragma unroll
        for (int jh = 0; jh < 2; jh++) {
            int col0 = bn * 128 + (jh ? (64 + tx * 4) : (tx * 4));
            float4 vv;
            float t[4];
            #pragma unroll
            for (int jj = 0; jj < 4; jj++) t[jj] = acc[i][jh * 4 + jj];
            if (bias) {
                #pragma unroll
                for (int jj = 0; jj < 4; jj++) t[jj] += bias[col0 + jj];
            }
            if (relu) {
                #pragma unroll
                for (int jj = 0; jj < 4; jj++) t[jj] = fmaxf(t[jj], 0.f);
            }
            if (res) {
                const float4 rv = *(const float4*)(res + (size_t)row * N + col0);
                t[0] += rv.x; t[1] += rv.y; t[2] += rv.z; t[3] += rv.w;
            }
            vv.x = t[0]; vv.y = t[1]; vv.z = t[2]; vv.w = t[3];
            *(float4*)(C + (size_t)row * N + col0) = vv;
        }
    }
}

// ---------------- fused flash attention --------------------------------------
// grid (S/64, NH, B), 256 threads. Q tile 64 rows, KV tiles of 64.
// smem: Qt[64][65] (Q^T, pre-scaled), KS[64][65] (K^T then P), Vs[64][64],
//       mrow/lrow/crow[64], msk[64]  => 50688 bytes dynamic
#define FA_SMEM ((64*65*2 + 64*64 + 64*3 + 64) * 4)

__global__ __launch_bounds__(256) void flash_kernel(
    const float* __restrict__ q, const float* __restrict__ k,
    const float* __restrict__ v, const int* __restrict__ mask,
    float* __restrict__ out)
{
    extern __shared__ float sm[];
    float* Qt   = sm;               // 64*65
    float* KS   = Qt + 64 * 65;     // 64*65  (K^T, reused as P)
    float* Vs   = KS + 64 * 65;     // 64*64
    float* mrow = Vs + 64 * 64;     // 64
    float* lrow = mrow + 64;        // 64
    float* crow = lrow + 64;        // 64
    int*   msk  = (int*)(crow + 64);// 64

    int q0 = blockIdx.x * 64;
    int h  = blockIdx.y;
    int b  = blockIdx.z;
    int tid = threadIdx.x;
    int tx = tid & 15, ty = tid >> 4;
    int r0 = ty * 4, c0 = tx * 4;

    const size_t base = ((size_t)b * S_) * EMB_ + (size_t)h * DK_;

    for (int idx = tid; idx < 64 * 64; idx += 256) {
        int r = idx >> 6, d = idx & 63;
        Qt[d * 65 + r] = q[base + (size_t)(q0 + r) * EMB_ + d] * 0.125f; // 1/sqrt(64)
    }
    if (tid < 64) { mrow[tid] = -1e30f; lrow[tid] = 0.f; }

    float o_[4][4];
    #pragma unroll
    for (int i = 0; i < 4; i++)
        #pragma unroll
        for (int j = 0; j < 4; j++) o_[i][j] = 0.f;

    for (int j0 = 0; j0 < S_; j0 += 64) {
        __syncthreads();   // protects KS/Vs reuse + first-iter init
        for (int idx = tid; idx < 64 * 64; idx += 256) {
            int r = idx >> 6, d = idx & 63;
            size_t g = base + (size_t)(j0 + r) * EMB_ + d;
            KS[d * 65 + r] = k[g];
            Vs[r * 64 + d] = v[g];
        }
        if (tid < 64) msk[tid] = mask[b * S_ + j0 + tid];
        __syncthreads();

        // S = (Q*scale) @ K^T  (4x4 per thread)
        float sv[4][4];
        #pragma unroll
        for (int i = 0; i < 4; i++)
            #pragma unroll
            for (int j = 0; j < 4; j++) sv[i][j] = 0.f;

        #pragma unroll 16
        for (int d = 0; d < 64; d++) {
            float qv[4], kv[4];
            #pragma unroll
            for (int i = 0; i < 4; i++) qv[i] = Qt[d * 65 + r0 + i];
            #pragma unroll
            for (int j = 0; j < 4; j++) kv[j] = KS[d * 65 + c0 + j];
            #pragma unroll
            for (int i = 0; i < 4; i++)
                #pragma unroll
                for (int j = 0; j < 4; j++)
                    sv[i][j] = fmaf(qv[i], kv[j], sv[i][j]);
        }
        __syncthreads();   // all done reading K^T before overwrite with S

        #pragma unroll
        for (int i = 0; i < 4; i++)
            #pragma unroll
            for (int j = 0; j < 4; j++) {
                float val = sv[i][j];
                if (msk[c0 + j] == 0) val = -1e30f;
                KS[(r0 + i) * 65 + (c0 + j)] = val;
            }
        __syncthreads();

        // online softmax per row (64 threads, one row each)
        if (tid < 64) {
            int r = tid;
            float mold = mrow[r], mx = mold;
            #pragma unroll 8
            for (int c = 0; c < 64; c++) mx = fmaxf(mx, KS[r * 65 + c]);
            float corr = __expf(mold - mx);
            float sum = 0.f;
            #pragma unroll 8
            for (int c = 0; c < 64; c++) {
                float p = __expf(KS[r * 65 + c] - mx);
                KS[r * 65 + c] = p;
                sum += p;
            }
            mrow[r] = mx;
            lrow[r] = lrow[r] * corr + sum;
            crow[r] = corr;
        }
        __syncthreads();

        // O = O*corr + P @ V
        float cr[4];
        #pragma unroll
        for (int i = 0; i < 4; i++) cr[i] = crow[r0 + i];
        #pragma unroll
        for (int i = 0; i < 4; i++)
            #pragma unroll
            for (int j = 0; j < 4; j++) o_[i][j] *= cr[i];

        #pragma unroll 16
        for (int jj = 0; jj < 64; jj++) {
            float pv[4], vv[4];
            #pragma unroll
            for (int i = 0; i < 4; i++) pv[i] = KS[(r0 + i) * 65 + jj];
            #pragma unroll
            for (int j = 0; j < 4; j++) vv[j] = Vs[jj * 64 + c0 + j];
            #pragma unroll
            for (int i = 0; i < 4; i++)
                #pragma unroll
                for (int j = 0; j < 4; j++)
                    o_[i][j] = fmaf(pv[i], vv[j], o_[i][j]);
        }
    }

    float inv[4];
    #pragma unroll
    for (int i = 0; i < 4; i++) inv[i] = 1.0f / lrow[r0 + i];
    #pragma unroll
    for (int i = 0; i < 4; i++)
        #pragma unroll
        for (int j = 0; j < 4; j++)
            out[base + (size_t)(q0 + r0 + i) * EMB_ + c0 + j] = o_[i][j] * inv[i];
}

// ---------------- launch -----------------------------------------------------
extern "C" void kernel_launch(void* const* d_in, const int* in_sizes, int n_in,
                              void* d_out, int out_size)
{
    const float* x     = (const float*)d_in[0];
    const int*   mask  = (const int*)  d_in[1];
    const float* wq    = (const float*)d_in[2];
    const float* wk    = (const float*)d_in[3];
    const float* wv    = (const float*)d_in[4];
    const float* wo    = (const float*)d_in[5];
    const float* ff1w  = (const float*)d_in[6];
    const float* ff1b  = (const float*)d_in[7];
    const float* ff2w  = (const float*)d_in[8];
    const float* ff2b  = (const float*)d_in[9];
    const float* ln1a  = (const float*)d_in[10];
    const float* ln1b  = (const float*)d_in[11];
    const float* ln2a  = (const float*)d_in[12];
    const float* ln2b  = (const float*)d_in[13];
    float* out = (float*)d_out;

    float *xn, *q, *k, *v, *ao, *h, *hn, *ff;
    cudaGetSymbolAddress((void**)&xn, g_xn);
    cudaGetSymbolAddress((void**)&q,  g_q);
    cudaGetSymbolAddress((void**)&k,  g_k);
    cudaGetSymbolAddress((void**)&v,  g_v);
    cudaGetSymbolAddress((void**)&ao, g_ao);
    cudaGetSymbolAddress((void**)&h,  g_h);
    cudaGetSymbolAddress((void**)&hn, g_hn);
    cudaGetSymbolAddress((void**)&ff, g_ff);

    cudaFuncSetAttribute(flash_kernel,
                         cudaFuncAttributeMaxDynamicSharedMemorySize, FA_SMEM);

    // 1) xn = LN1(x)
    ln_kernel<<<ROWS_, 256>>>(x, xn, ln1a, ln1b);

    // 2) q,k,v = xn @ {wq,wk,wv}
    sgemm_kernel<<<dim3(EMB_/128, ROWS_/128), 256>>>(ROWS_, EMB_, EMB_, xn, wq, q, nullptr, nullptr, 0);
    sgemm_kernel<<<dim3(EMB_/128, ROWS_/128), 256>>>(ROWS_, EMB_, EMB_, xn, wk, k, nullptr, nullptr, 0);
    sgemm_kernel<<<dim3(EMB_/128, ROWS_/128), 256>>>(ROWS_, EMB_, EMB_, xn, wv, v, nullptr, nullptr, 0);

    // 3) ao = softmax(q k^T / sqrt(dk) + mask) v   (fused flash)
    flash_kernel<<<dim3(S_/64, NH_, B_), 256, FA_SMEM>>>(q, k, v, mask, ao);

    // 4) h = x + ao @ wo
    sgemm_kernel<<<dim3(EMB_/128, ROWS_/128), 256>>>(ROWS_, EMB_, EMB_, ao, wo, h, nullptr, x, 0);

    // 5) hn = LN2(h)
    ln_kernel<<<ROWS_, 256>>>(h, hn, ln2a, ln2b);

    // 6) ff = relu(hn @ ff1w + ff1b)
    sgemm_kernel<<<dim3(HID_/128, ROWS_/128), 256>>>(ROWS_, HID_, EMB_, hn, ff1w, ff, ff1b, nullptr, 1);

    // 7) out = h + ff @ ff2w + ff2b
    sgemm_kernel<<<dim3(EMB_/128, ROWS_/128), 256>>>(ROWS_, EMB_, HID_, ff, ff2w, out, ff2b, h, 0);
}

// round 7
// speedup vs baseline: 1.3974x; 1.3974x over previous
#include <cuda_runtime.h>
#include <cuda_bf16.h>
#include <math.h>
#include <stdint.h>

#define B_   2
#define S_   2048
#define EMB_ 1024
#define HID_ 4096
#define NH_  16
#define DK_  64
#define ROWS_ (B_*S_)   // 4096

// ---------------- scratch (static device arrays; no allocation APIs) ---------
__device__ float g_xn[ROWS_*EMB_];
__device__ float g_q [ROWS_*EMB_];
__device__ float g_k [ROWS_*EMB_];
__device__ float g_v [ROWS_*EMB_];
__device__ float g_ao[ROWS_*EMB_];
__device__ float g_h [ROWS_*EMB_];
__device__ float g_hn[ROWS_*EMB_];
__device__ float g_ff[ROWS_*HID_];

// ================= helpers ===================================================
__device__ __forceinline__ uint32_t smem_u32(const void* p) {
    uint32_t a;
    asm("{ .reg .u64 t; cvta.to.shared.u64 t, %1; cvt.u32.u64 %0, t; }" : "=r"(a) : "l"(p));
    return a;
}
__device__ __forceinline__ uint32_t pack_bf16(__nv_bfloat16 a, __nv_bfloat16 b) {
    return (uint32_t)__bfloat16_as_ushort(a) | ((uint32_t)__bfloat16_as_ushort(b) << 16);
}
__device__ __forceinline__ void ldsm_x4(uint32_t* r, uint32_t addr) {
    asm volatile("ldmatrix.sync.aligned.m8n8.x4.shared.b16 {%0,%1,%2,%3}, [%4];"
                 : "=r"(r[0]), "=r"(r[1]), "=r"(r[2]), "=r"(r[3]) : "r"(addr));
}
__device__ __forceinline__ void ldsm_x4t(uint32_t* r, uint32_t addr) {
    asm volatile("ldmatrix.sync.aligned.m8n8.x4.trans.shared.b16 {%0,%1,%2,%3}, [%4];"
                 : "=r"(r[0]), "=r"(r[1]), "=r"(r[2]), "=r"(r[3]) : "r"(addr));
}
__device__ __forceinline__ void mma_bf16(float* c, const uint32_t* a, uint32_t b0, uint32_t b1) {
    asm volatile("mma.sync.aligned.m16n8k16.row.col.f32.bf16.bf16.f32 "
                 "{%0,%1,%2,%3}, {%4,%5,%6,%7}, {%8,%9}, {%0,%1,%2,%3};"
                 : "+f"(c[0]), "+f"(c[1]), "+f"(c[2]), "+f"(c[3])
                 : "r"(a[0]), "r"(a[1]), "r"(a[2]), "r"(a[3]), "r"(b0), "r"(b1));
}

// ================= bf16x3 GEMM via mma.sync ==================================
// C[M,N] = A[M,K](fp32) @ W[K,N](fp32)  (+bias) (relu) (+res)
// Tiles 128x128, BK=32. 256 threads = 8 warps (4m x 2n), warp tile 32x64.
#define A_STRIDE 40    // bf16 elems per row (80B: conflict-free ldmatrix)
#define B_STRIDE 136   // bf16 elems per row (272B: conflict-free ldmatrix.trans)

__global__ __launch_bounds__(256) void gemm_mma(
    int K, int N,
    const float* __restrict__ A, const float* __restrict__ W,
    float* __restrict__ C,
    const float* __restrict__ bias, const float* __restrict__ res, int relu)
{
    __shared__ __align__(16) __nv_bfloat16 As_h[128 * A_STRIDE];
    __shared__ __align__(16) __nv_bfloat16 As_l[128 * A_STRIDE];
    __shared__ __align__(16) __nv_bfloat16 Bs_h[32 * B_STRIDE];
    __shared__ __align__(16) __nv_bfloat16 Bs_l[32 * B_STRIDE];

    const int tid = threadIdx.x;
    const int lane = tid & 31;
    const int wid = tid >> 5;
    const int warp_m = wid & 3;        // 0..3  -> 32 rows each
    const int warp_n = wid >> 2;       // 0..1  -> 64 cols each
    const int m0 = blockIdx.y * 128;
    const int n0 = blockIdx.x * 128;

    const uint32_t sAh = smem_u32(As_h), sAl = smem_u32(As_l);
    const uint32_t sBh = smem_u32(Bs_h), sBl = smem_u32(Bs_l);

    // ldmatrix base addresses (per-lane)
    // A (non-trans): row = warp_m*32 + mi*16 + lane%16, col byte = (kk + (lane/16)*8)*2
    const uint32_t aRow = (uint32_t)(warp_m * 32 + (lane & 15));
    const uint32_t aColB = (uint32_t)((lane >> 4) * 16);
    // B (trans): row k = kk + lane%16, col byte = (warp_n*64 + np*16 + (lane/16)*8)*2
    const uint32_t bRowK = (uint32_t)(lane & 15);
    const uint32_t bColB = (uint32_t)(warp_n * 128 + (lane >> 4) * 16);

    float acc[2][8][4];
    #pragma unroll
    for (int mi = 0; mi < 2; mi++)
        #pragma unroll
        for (int nf = 0; nf < 8; nf++)
            #pragma unroll
            for (int e = 0; e < 4; e++) acc[mi][nf][e] = 0.f;

    const int nch = K >> 5;
    for (int c = 0; c < nch; c++) {
        const int k0 = c << 5;
        __syncthreads();

        // ---- A tile: 128 x 32 fp32 -> hi/lo bf16, layout [m][k] ----
        #pragma unroll
        for (int i = 0; i < 4; i++) {
            int idx = tid + i * 256;       // 0..1023
            int m = idx >> 3, f = idx & 7; // f: float4 index (4 k vals)
            float4 v = *(const float4*)(A + (size_t)(m0 + m) * K + k0 + f * 4);
            __nv_bfloat16 h0 = __float2bfloat16(v.x), h1 = __float2bfloat16(v.y);
            __nv_bfloat16 h2 = __float2bfloat16(v.z), h3 = __float2bfloat16(v.w);
            __nv_bfloat16 l0 = __float2bfloat16(v.x - __bfloat162float(h0));
            __nv_bfloat16 l1 = __float2bfloat16(v.y - __bfloat162float(h1));
            __nv_bfloat16 l2 = __float2bfloat16(v.z - __bfloat162float(h2));
            __nv_bfloat16 l3 = __float2bfloat16(v.w - __bfloat162float(h3));
            int o = m * A_STRIDE + f * 4;
            *(uint2*)&As_h[o] = make_uint2(pack_bf16(h0, h1), pack_bf16(h2, h3));
            *(uint2*)&As_l[o] = make_uint2(pack_bf16(l0, l1), pack_bf16(l2, l3));
        }
        // ---- B tile: 32 x 128 fp32 -> hi/lo bf16, layout [k][n] (no transpose) ----
        #pragma unroll
        for (int i = 0; i < 4; i++) {
            int idx = tid + i * 256;         // 0..1023
            int kk = idx >> 5, g = idx & 31; // g: float4 index (4 n vals)
            float4 v = *(const float4*)(W + (size_t)(k0 + kk) * N + n0 + g * 4);
            __nv_bfloat16 h0 = __float2bfloat16(v.x), h1 = __float2bfloat16(v.y);
            __nv_bfloat16 h2 = __float2bfloat16(v.z), h3 = __float2bfloat16(v.w);
            __nv_bfloat16 l0 = __float2bfloat16(v.x - __bfloat162float(h0));
            __nv_bfloat16 l1 = __float2bfloat16(v.y - __bfloat162float(h1));
            __nv_bfloat16 l2 = __float2bfloat16(v.z - __bfloat162float(h2));
            __nv_bfloat16 l3 = __float2bfloat16(v.w - __bfloat162float(h3));
            int o = kk * B_STRIDE + g * 4;
            *(uint2*)&Bs_h[o] = make_uint2(pack_bf16(h0, h1), pack_bf16(h2, h3));
            *(uint2*)&Bs_l[o] = make_uint2(pack_bf16(l0, l1), pack_bf16(l2, l3));
        }
        __syncthreads();

        #pragma unroll
        for (int ks = 0; ks < 2; ks++) {   // kk = 0, 16
            const uint32_t kk = ks * 16;
            uint32_t ah[2][4], al[2][4];
            #pragma unroll
            for (int mi = 0; mi < 2; mi++) {
                uint32_t off = (aRow + mi * 16) * (A_STRIDE * 2) + kk * 2 + aColB;
                ldsm_x4(ah[mi], sAh + off);
                ldsm_x4(al[mi], sAl + off);
            }
            #pragma unroll
            for (int np = 0; np < 4; np++) {
                uint32_t bh[4], bl[4];
                uint32_t off = (kk + bRowK) * (B_STRIDE * 2) + np * 32 + bColB;
                ldsm_x4t(bh, sBh + off);
                ldsm_x4t(bl, sBl + off);
                #pragma unroll
                for (int mi = 0; mi < 2; mi++) {
                    mma_bf16(acc[mi][2 * np],     ah[mi], bh[0], bh[1]);
                    mma_bf16(acc[mi][2 * np + 1], ah[mi], bh[2], bh[3]);
                    mma_bf16(acc[mi][2 * np],     al[mi], bh[0], bh[1]);
                    mma_bf16(acc[mi][2 * np + 1], al[mi], bh[2], bh[3]);
                    mma_bf16(acc[mi][2 * np],     ah[mi], bl[0], bl[1]);
                    mma_bf16(acc[mi][2 * np + 1], ah[mi], bl[2], bl[3]);
                }
            }
        }
    }

    // ---- epilogue from register fragments ----
    const int r_in = lane >> 2;
    const int cp = (lane & 3) * 2;
    #pragma unroll
    for (int mi = 0; mi < 2; mi++) {
        #pragma unroll
        for (int nf = 0; nf < 8; nf++) {
            int gn = n0 + warp_n * 64 + nf * 8 + cp;
            float2 bb = make_float2(0.f, 0.f);
            if (bias) bb = *(const float2*)(bias + gn);
            #pragma unroll
            for (int half = 0; half < 2; half++) {
                int gm = m0 + warp_m * 32 + mi * 16 + r_in + half * 8;
                float2 t;
                t.x = acc[mi][nf][half * 2 + 0] + bb.x;
                t.y = acc[mi][nf][half * 2 + 1] + bb.y;
                if (relu) { t.x = fmaxf(t.x, 0.f); t.y = fmaxf(t.y, 0.f); }
                if (res) {
                    float2 rv = *(const float2*)(res + (size_t)gm * N + gn);
                    t.x += rv.x; t.y += rv.y;
                }
                *(float2*)(C + (size_t)gm * N + gn) = t;
            }
        }
    }
}

// ---------------- block-wide sum --------------------------------------------
__device__ __forceinline__ float block_sum(float val) {
    __shared__ float red[8];
    int lane = threadIdx.x & 31, w = threadIdx.x >> 5;
    #pragma unroll
    for (int o = 16; o; o >>= 1) val += __shfl_xor_sync(0xffffffffu, val, o);
    if (lane == 0) red[w] = val;
    __syncthreads();
    if (w == 0) {
        float t = (lane < 8) ? red[lane] : 0.f;
        #pragma unroll
        for (int o = 4; o; o >>= 1) t += __shfl_xor_sync(0xffffffffu, t, o);
        if (lane == 0) red[0] = t;
    }
    __syncthreads();
    float r = red[0];
    __syncthreads();
    return r;
}

// ---------------- LayerNorm (Bessel-corrected, std+eps) ----------------------
__global__ __launch_bounds__(256) void ln_kernel(
    const float* __restrict__ x, float* __restrict__ y,
    const float* __restrict__ a, const float* __restrict__ b)
{
    int row = blockIdx.x;
    const float4* xr = (const float4*)(x + (size_t)row * EMB_);
    float4 v = xr[threadIdx.x];
    float s = v.x + v.y + v.z + v.w;
    float total = block_sum(s);
    float mean = total * (1.0f / EMB_);
    float4 d;
    d.x = v.x - mean; d.y = v.y - mean; d.z = v.z - mean; d.w = v.w - mean;
    float ss = d.x*d.x + d.y*d.y + d.z*d.z + d.w*d.w;
    float sstot = block_sum(ss);
    float var = sstot * (1.0f / (EMB_ - 1));
    float scale = a[0] / (sqrtf(var) + 1e-6f);
    float bb = b[0];
    float4 o;
    o.x = d.x * scale + bb; o.y = d.y * scale + bb;
    o.z = d.z * scale + bb; o.w = d.w * scale + bb;
    ((float4*)(y + (size_t)row * EMB_))[threadIdx.x] = o;
}

// ---------------- fused flash attention (unchanged from R2) ------------------
#define FA_SMEM ((64*65*2 + 64*64 + 64*3 + 64) * 4)

__global__ __launch_bounds__(256) void flash_kernel(
    const float* __restrict__ q, const float* __restrict__ k,
    const float* __restrict__ v, const int* __restrict__ mask,
    float* __restrict__ out)
{
    extern __shared__ float smf[];
    float* Qt   = smf;
    float* KS   = Qt + 64 * 65;
    float* Vs   = KS + 64 * 65;
    float* mrow = Vs + 64 * 64;
    float* lrow = mrow + 64;
    float* crow = lrow + 64;
    int*   msk  = (int*)(crow + 64);

    int q0 = blockIdx.x * 64;
    int h  = blockIdx.y;
    int b  = blockIdx.z;
    int tid = threadIdx.x;
    int tx = tid & 15, ty = tid >> 4;
    int r0 = ty * 4, c0 = tx * 4;

    const size_t base = ((size_t)b * S_) * EMB_ + (size_t)h * DK_;

    for (int idx = tid; idx < 64 * 64; idx += 256) {
        int r = idx >> 6, d = idx & 63;
        Qt[d * 65 + r] = q[base + (size_t)(q0 + r) * EMB_ + d] * 0.125f;
    }
    if (tid < 64) { mrow[tid] = -1e30f; lrow[tid] = 0.f; }

    float o_[4][4];
    #pragma unroll
    for (int i = 0; i < 4; i++)
        #pragma unroll
        for (int j = 0; j < 4; j++) o_[i][j] = 0.f;

    for (int j0 = 0; j0 < S_; j0 += 64) {
        __syncthreads();
        for (int idx = tid; idx < 64 * 64; idx += 256) {
            int r = idx >> 6, d = idx & 63;
            size_t g = base + (size_t)(j0 + r) * EMB_ + d;
            KS[d * 65 + r] = k[g];
            Vs[r * 64 + d] = v[g];
        }
        if (tid < 64) msk[tid] = mask[b * S_ + j0 + tid];
        __syncthreads();

        float sv[4][4];
        #pragma unroll
        for (int i = 0; i < 4; i++)
            #pragma unroll
            for (int j = 0; j < 4; j++) sv[i][j] = 0.f;

        #pragma unroll 16
        for (int d = 0; d < 64; d++) {
            float qv[4], kv[4];
            #pragma unroll
            for (int i = 0; i < 4; i++) qv[i] = Qt[d * 65 + r0 + i];
            #pragma unroll
            for (int j = 0; j < 4; j++) kv[j] = KS[d * 65 + c0 + j];
            #pragma unroll
            for (int i = 0; i < 4; i++)
                #pragma unroll
                for (int j = 0; j < 4; j++)
                    sv[i][j] = fmaf(qv[i], kv[j], sv[i][j]);
        }
        __syncthreads();

        #pragma unroll
        for (int i = 0; i < 4; i++)
            #pragma unroll
            for (int j = 0; j < 4; j++) {
                float val = sv[i][j];
                if (msk[c0 + j] == 0) val = -1e30f;
                KS[(r0 + i) * 65 + (c0 + j)] = val;
            }
        __syncthreads();

        if (tid < 64) {
            int r = tid;
            float mold = mrow[r], mx = mold;
            #pragma unroll 8
            for (int c = 0; c < 64; c++) mx = fmaxf(mx, KS[r * 65 + c]);
            float corr = __expf(mold - mx);
            float sum = 0.f;
            #pragma unroll 8
            for (int c = 0; c < 64; c++) {
                float p = __expf(KS[r * 65 + c] - mx);
                KS[r * 65 + c] = p;
                sum += p;
            }
            mrow[r] = mx;
            lrow[r] = lrow[r] * corr + sum;
            crow[r] = corr;
        }
        __syncthreads();

        float cr[4];
        #pragma unroll
        for (int i = 0; i < 4; i++) cr[i] = crow[r0 + i];
        #pragma unroll
        for (int i = 0; i < 4; i++)
            #pragma unroll
            for (int j = 0; j < 4; j++) o_[i][j] *= cr[i];

        #pragma unroll 16
        for (int jj = 0; jj < 64; jj++) {
            float pv[4], vv[4];
            #pragma unroll
            for (int i = 0; i < 4; i++) pv[i] = KS[(r0 + i) * 65 + jj];
            #pragma unroll
            for (int j = 0; j < 4; j++) vv[j] = Vs[jj * 64 + c0 + j];
            #pragma unroll
            for (int i = 0; i < 4; i++)
                #pragma unroll
                for (int j = 0; j < 4; j++)
                    o_[i][j] = fmaf(pv[i], vv[j], o_[i][j]);
        }
    }

    float inv[4];
    #pragma unroll
    for (int i = 0; i < 4; i++) inv[i] = 1.0f / lrow[r0 + i];
    #pragma unroll
    for (int i = 0; i < 4; i++)
        #pragma unroll
        for (int j = 0; j < 4; j++)
            out[base + (size_t)(q0 + r0 + i) * EMB_ + c0 + j] = o_[i][j] * inv[i];
}

// ---------------- launch -----------------------------------------------------
extern "C" void kernel_launch(void* const* d_in, const int* in_sizes, int n_in,
                              void* d_out, int out_size)
{
    const float* x     = (const float*)d_in[0];
    const int*   mask  = (const int*)  d_in[1];
    const float* wq    = (const float*)d_in[2];
    const float* wk    = (const float*)d_in[3];
    const float* wv    = (const float*)d_in[4];
    const float* wo    = (const float*)d_in[5];
    const float* ff1w  = (const float*)d_in[6];
    const float* ff1b  = (const float*)d_in[7];
    const float* ff2w  = (const float*)d_in[8];
    const float* ff2b  = (const float*)d_in[9];
    const float* ln1a  = (const float*)d_in[10];
    const float* ln1b  = (const float*)d_in[11];
    const float* ln2a  = (const float*)d_in[12];
    const float* ln2b  = (const float*)d_in[13];
    float* out = (float*)d_out;

    float *xn, *q, *k, *v, *ao, *h, *hn, *ff;
    cudaGetSymbolAddress((void**)&xn, g_xn);
    cudaGetSymbolAddress((void**)&q,  g_q);
    cudaGetSymbolAddress((void**)&k,  g_k);
    cudaGetSymbolAddress((void**)&v,  g_v);
    cudaGetSymbolAddress((void**)&ao, g_ao);
    cudaGetSymbolAddress((void**)&h,  g_h);
    cudaGetSymbolAddress((void**)&hn, g_hn);
    cudaGetSymbolAddress((void**)&ff, g_ff);

    cudaFuncSetAttribute(flash_kernel,
                         cudaFuncAttributeMaxDynamicSharedMemorySize, FA_SMEM);

    // 1) xn = LN1(x)
    ln_kernel<<<ROWS_, 256>>>(x, xn, ln1a, ln1b);

    // 2) q,k,v = xn @ {wq,wk,wv}
    gemm_mma<<<dim3(EMB_/128, ROWS_/128), 256>>>(EMB_, EMB_, xn, wq, q, nullptr, nullptr, 0);
    gemm_mma<<<dim3(EMB_/128, ROWS_/128), 256>>>(EMB_, EMB_, xn, wk, k, nullptr, nullptr, 0);
    gemm_mma<<<dim3(EMB_/128, ROWS_/128), 256>>>(EMB_, EMB_, xn, wv, v, nullptr, nullptr, 0);

    // 3) ao = softmax(q k^T / sqrt(dk)) v
    flash_kernel<<<dim3(S_/64, NH_, B_), 256, FA_SMEM>>>(q, k, v, mask, ao);

    // 4) h = x + ao @ wo
    gemm_mma<<<dim3(EMB_/128, ROWS_/128), 256>>>(EMB_, EMB_, ao, wo, h, nullptr, x, 0);

    // 5) hn = LN2(h)
    ln_kernel<<<ROWS_, 256>>>(h, hn, ln2a, ln2b);

    // 6) ff = relu(hn @ ff1w + ff1b)
    gemm_mma<<<dim3(HID_/128, ROWS_/128), 256>>>(EMB_, HID_, hn, ff1w, ff, ff1b, nullptr, 1);

    // 7) out = h + ff @ ff2w + ff2b
    gemm_mma<<<dim3(EMB_/128, ROWS_/128), 256>>>(HID_, EMB_, ff, ff2w, out, ff2b, h, 0);
}